// round 2
// baseline (speedup 1.0000x reference)
#include <cuda_runtime.h>
#include <cuda_bf16.h>
#include <math.h>

#define BDIM 8
#define NDIM 1024
#define DDIM 256
#define HDIM 8
#define UDIM 64
#define HU   512
#define ROWS (BDIM*NDIM)   // 8192

// Scratch (static device globals — no allocations allowed)
__device__ float          g_feat [ROWS*HU];
__device__ float          g_resid[ROWS*HU];
__device__ __nv_bfloat16  g_fbf  [ROWS*HU];   // bf16 shadow of g_feat (gather path)
__device__ float          g_aself[ROWS*HDIM];
__device__ float          g_aneigh[ROWS*HDIM];

// ---------------------------------------------------------------------------
// Kernel A: fp32 GEMM, C = X[8192,256] @ W[256,512], double-buffered smem.
// blockIdx.z selects (kernel -> g_feat) or (kernel_residual -> g_resid).
// 128x128 tile, BK=16, 256 threads, 8x8 microtile per thread.
// ---------------------------------------------------------------------------
__global__ __launch_bounds__(256) void proj_gemm(const float* __restrict__ Xg,
                                                 const float* __restrict__ W0,
                                                 const float* __restrict__ W1)
{
    const float* W = (blockIdx.z == 0) ? W0 : W1;
    float*       C = (blockIdx.z == 0) ? g_feat : g_resid;

    __shared__ __align__(16) float As[2][16][132];  // transposed [k][m], +4 pad
    __shared__ __align__(16) float Bs[2][16][128];

    const int tid = threadIdx.x;
    const int bm  = blockIdx.y * 128;
    const int bn  = blockIdx.x * 128;
    const int tx  = tid & 15;
    const int ty  = tid >> 4;

    // per-iteration load geometry (2 float4 for A, 2 for B per thread)
    const int aIdx0 = tid * 2;             // 0..510
    const int aRow0 = aIdx0 >> 2;          // 0..127
    const int aC40  = (aIdx0 & 3) << 2;
    const int aIdx1 = tid * 2 + 1;
    const int aRow1 = aIdx1 >> 2;
    const int aC41  = (aIdx1 & 3) << 2;
    const int bRow0 = aIdx0 >> 5;          // 0..15
    const int bC40  = (aIdx0 & 31) << 2;
    const int bRow1 = aIdx1 >> 5;
    const int bC41  = (aIdx1 & 31) << 2;

    const float* Ap0 = Xg + (size_t)(bm + aRow0) * DDIM + aC40;
    const float* Ap1 = Xg + (size_t)(bm + aRow1) * DDIM + aC41;
    const float* Bp0 = W  + (size_t)bRow0 * HU + bn + bC40;
    const float* Bp1 = W  + (size_t)bRow1 * HU + bn + bC41;

    float acc[8][8];
#pragma unroll
    for (int i = 0; i < 8; i++)
#pragma unroll
        for (int j = 0; j < 8; j++) acc[i][j] = 0.f;

    float4 ra0, ra1, rb0, rb1;

    // prologue: load k-tile 0 into buffer 0
    ra0 = *(const float4*)(Ap0);
    ra1 = *(const float4*)(Ap1);
    rb0 = *(const float4*)(Bp0);
    rb1 = *(const float4*)(Bp1);
    As[0][aC40 + 0][aRow0] = ra0.x; As[0][aC40 + 1][aRow0] = ra0.y;
    As[0][aC40 + 2][aRow0] = ra0.z; As[0][aC40 + 3][aRow0] = ra0.w;
    As[0][aC41 + 0][aRow1] = ra1.x; As[0][aC41 + 1][aRow1] = ra1.y;
    As[0][aC41 + 2][aRow1] = ra1.z; As[0][aC41 + 3][aRow1] = ra1.w;
    *(float4*)&Bs[0][bRow0][bC40] = rb0;
    *(float4*)&Bs[0][bRow1][bC41] = rb1;
    __syncthreads();

#pragma unroll
    for (int t = 0; t < 16; t++) {
        const int cur = t & 1;
        if (t < 15) {
            const int koff = (t + 1) * 16;
            ra0 = *(const float4*)(Ap0 + koff);
            ra1 = *(const float4*)(Ap1 + koff);
            rb0 = *(const float4*)(Bp0 + (size_t)koff * HU);
            rb1 = *(const float4*)(Bp1 + (size_t)koff * HU);
        }
#pragma unroll
        for (int kk = 0; kk < 16; kk++) {
            float a[8], b[8];
            *(float4*)(a)     = *(const float4*)&As[cur][kk][ty * 8];
            *(float4*)(a + 4) = *(const float4*)&As[cur][kk][ty * 8 + 4];
            *(float4*)(b)     = *(const float4*)&Bs[cur][kk][tx * 8];
            *(float4*)(b + 4) = *(const float4*)&Bs[cur][kk][tx * 8 + 4];
#pragma unroll
            for (int i = 0; i < 8; i++)
#pragma unroll
                for (int j = 0; j < 8; j++)
                    acc[i][j] = fmaf(a[i], b[j], acc[i][j]);
        }
        if (t < 15) {
            const int nxt = cur ^ 1;
            As[nxt][aC40 + 0][aRow0] = ra0.x; As[nxt][aC40 + 1][aRow0] = ra0.y;
            As[nxt][aC40 + 2][aRow0] = ra0.z; As[nxt][aC40 + 3][aRow0] = ra0.w;
            As[nxt][aC41 + 0][aRow1] = ra1.x; As[nxt][aC41 + 1][aRow1] = ra1.y;
            As[nxt][aC41 + 2][aRow1] = ra1.z; As[nxt][aC41 + 3][aRow1] = ra1.w;
            *(float4*)&Bs[nxt][bRow0][bC40] = rb0;
            *(float4*)&Bs[nxt][bRow1][bC41] = rb1;
            __syncthreads();
        }
    }

#pragma unroll
    for (int i = 0; i < 8; i++) {
        size_t off = (size_t)(bm + ty * 8 + i) * HU + bn + tx * 8;
        *(float4*)(C + off)     = make_float4(acc[i][0], acc[i][1], acc[i][2], acc[i][3]);
        *(float4*)(C + off + 4) = make_float4(acc[i][4], acc[i][5], acc[i][6], acc[i][7]);
    }
}

// ---------------------------------------------------------------------------
// Kernel B: per-row additive-attention logits + bf16 shadow copy of f.
// One block per row, 512 threads (one per unit).
// ---------------------------------------------------------------------------
__global__ __launch_bounds__(512) void attn_logits(const float* __restrict__ aks,
                                                   const float* __restrict__ akn)
{
    const int row = blockIdx.x;
    const int tid = threadIdx.x;

    float fv = g_feat[(size_t)row * HU + tid];

    // bf16 shadow write (pairwise via shfl, 4B stores from even lanes)
    float fo = __shfl_down_sync(0xffffffffu, fv, 1);
    if ((tid & 1) == 0) {
        __nv_bfloat162 p = __floats2bfloat162_rn(fv, fo);
        *(__nv_bfloat162*)(g_fbf + (size_t)row * HU + tid) = p;
    }

    float s  = fv * aks[tid];
    float nn = fv * akn[tid];
#pragma unroll
    for (int off = 16; off; off >>= 1) {
        s  += __shfl_xor_sync(0xffffffffu, s,  off);
        nn += __shfl_xor_sync(0xffffffffu, nn, off);
    }
    __shared__ float ps[16], pn[16];
    int warp = tid >> 5;
    if ((tid & 31) == 0) { ps[warp] = s; pn[warp] = nn; }
    __syncthreads();
    if (tid < HDIM) {
        g_aself [row * HDIM + tid] = ps[2 * tid] + ps[2 * tid + 1];
        g_aneigh[row * HDIM + tid] = pn[2 * tid] + pn[2 * tid + 1];
    }
}

// ---------------------------------------------------------------------------
// Kernel C: sparse masked softmax + neighborhood aggregation + epilogue.
// One block per (b,n) row. Masked entries in the reference get logit-1e10,
// whose exp underflows to exactly 0.0f, so restricting to edges is bit-exact.
// Aggregation gathers f in bf16 (halved L2 traffic); coefs + accum in fp32.
// ---------------------------------------------------------------------------
__global__ __launch_bounds__(256) void gat_agg(const float* __restrict__ A,
                                               const float* __restrict__ bias,
                                               float* __restrict__ out)
{
    const int row  = blockIdx.x;      // b*1024 + n
    const int b    = row >> 10;
    const int tid  = threadIdx.x;
    const int lane = tid & 31;
    const int warp = tid >> 5;

    __shared__ int   nidx[NDIM];
    __shared__ float w[NDIM * HDIM];      // 32 KB: per-edge per-head weight
    __shared__ int   s_cnt;
    __shared__ float aself[HDIM];
    __shared__ float wred[8][HDIM];
    __shared__ float hval[HDIM];

    if (tid == 0) s_cnt = 0;
    if (tid < HDIM) aself[tid] = g_aself[row * HDIM + tid];
    __syncthreads();

    // ---- collect edges: A[b,n,:] is exactly 0.0/1.0 ----
    {
        float4 av = *(const float4*)(A + (size_t)row * NDIM + tid * 4);
        int base = tid * 4;
        if (av.x != 0.f) nidx[atomicAdd(&s_cnt, 1)] = base;
        if (av.y != 0.f) nidx[atomicAdd(&s_cnt, 1)] = base + 1;
        if (av.z != 0.f) nidx[atomicAdd(&s_cnt, 1)] = base + 2;
        if (av.w != 0.f) nidx[atomicAdd(&s_cnt, 1)] = base + 3;
    }
    __syncthreads();
    const int nnz = s_cnt;

    // ---- logits + per-head running max ----
    float lmax[HDIM];
#pragma unroll
    for (int h = 0; h < HDIM; h++) lmax[h] = -INFINITY;
    const float* an_b = g_aneigh + (size_t)b * NDIM * HDIM;
    for (int e = tid; e < nnz; e += 256) {
        int k = nidx[e];
        const float* an = an_b + k * HDIM;
#pragma unroll
        for (int h = 0; h < HDIM; h++) {
            float x = aself[h] + an[h];
            x = (x > 0.f) ? x : 0.2f * x;          // leaky_relu(0.2)
            w[e * HDIM + h] = x;
            lmax[h] = fmaxf(lmax[h], x);
        }
    }
#pragma unroll
    for (int h = 0; h < HDIM; h++)
#pragma unroll
        for (int off = 16; off; off >>= 1)
            lmax[h] = fmaxf(lmax[h], __shfl_xor_sync(0xffffffffu, lmax[h], off));
    if (lane == 0) {
#pragma unroll
        for (int h = 0; h < HDIM; h++) wred[warp][h] = lmax[h];
    }
    __syncthreads();
    if (tid < HDIM) {
        float m = wred[0][tid];
#pragma unroll
        for (int wp = 1; wp < 8; wp++) m = fmaxf(m, wred[wp][tid]);
        hval[tid] = m;
    }
    __syncthreads();
    float hm[HDIM];
#pragma unroll
    for (int h = 0; h < HDIM; h++) hm[h] = hval[h];

    // ---- exp + per-head sum ----
    float lsum[HDIM];
#pragma unroll
    for (int h = 0; h < HDIM; h++) lsum[h] = 0.f;
    for (int e = tid; e < nnz; e += 256) {
#pragma unroll
        for (int h = 0; h < HDIM; h++) {
            float v = __expf(w[e * HDIM + h] - hm[h]);
            w[e * HDIM + h] = v;
            lsum[h] += v;
        }
    }
#pragma unroll
    for (int h = 0; h < HDIM; h++)
#pragma unroll
        for (int off = 16; off; off >>= 1)
            lsum[h] += __shfl_xor_sync(0xffffffffu, lsum[h], off);
    if (lane == 0) {
#pragma unroll
        for (int h = 0; h < HDIM; h++) wred[warp][h] = lsum[h];
    }
    __syncthreads();
    if (tid < HDIM) {
        float s = 0.f;
#pragma unroll
        for (int wp = 0; wp < 8; wp++) s += wred[wp][tid];
        hval[tid] = 1.0f / s;
    }
    __syncthreads();
#pragma unroll
    for (int h = 0; h < HDIM; h++) hm[h] = hval[h];   // inverse sums now
    for (int e = tid; e < nnz; e += 256) {
#pragma unroll
        for (int h = 0; h < HDIM; h++) w[e * HDIM + h] *= hm[h];
    }
    __syncthreads();

    // ---- aggregate: out[row, 2t:2t+2] = sum_e coef[e, h] * fbf[b, k_e, 2t:2t+2]
    //      h = warp id (each warp owns one head; coef LDS is a broadcast) ----
    const int u = 2 * tid;            // 0..510
    const int h = warp;               // u/64 == tid/32
    const __nv_bfloat16* fb = g_fbf + (size_t)b * NDIM * HU + u;
    float acc0 = 0.f, acc1 = 0.f;
#pragma unroll 4
    for (int e = 0; e < nnz; e++) {
        int k = nidx[e];
        float c = w[e * HDIM + h];
        __nv_bfloat162 p = *(const __nv_bfloat162*)(fb + (size_t)k * HU);
        float2 f2 = __bfloat1622float2(p);
        acc0 = fmaf(c, f2.x, acc0);
        acc1 = fmaf(c, f2.y, acc1);
    }

    size_t o = (size_t)row * HU + u;
    float2 rres = *(const float2*)(g_resid + o);
    float r0 = acc0 + rres.x + bias[u];
    float r1 = acc1 + rres.y + bias[u + 1];
    float2 ro;
    ro.x = (r0 > 0.f) ? r0 : 0.f;
    ro.y = (r1 > 0.f) ? r1 : 0.f;
    *(float2*)(out + o) = ro;
}

// ---------------------------------------------------------------------------
extern "C" void kernel_launch(void* const* d_in, const int* in_sizes, int n_in,
                              void* d_out, int out_size)
{
    const float* X    = (const float*)d_in[0];  // [8,1024,256]
    const float* A    = (const float*)d_in[1];  // [8,1024,1024]
    const float* Wk   = (const float*)d_in[2];  // [256,512]
    const float* Wr   = (const float*)d_in[3];  // [256,512]
    const float* aks  = (const float*)d_in[4];  // [8,64,1] -> flat 512
    const float* akn  = (const float*)d_in[5];  // [8,64,1] -> flat 512
    const float* bias = (const float*)d_in[6];  // [512]
    float*       out  = (float*)d_out;          // [8,1024,512]

    (void)in_sizes; (void)n_in; (void)out_size;

    dim3 g(HU / 128, ROWS / 128, 2);
    proj_gemm<<<g, 256>>>(X, Wk, Wr);
    attn_logits<<<ROWS, 512>>>(aks, akn);
    gat_agg<<<ROWS, 256>>>(A, bias, out);
}

// round 3
// speedup vs baseline: 1.3178x; 1.3178x over previous
#include <cuda_runtime.h>
#include <cuda_bf16.h>
#include <math.h>

#define BDIM 8
#define NDIM 1024
#define DDIM 256
#define HDIM 8
#define UDIM 64
#define HU   512
#define ROWS (BDIM*NDIM)   // 8192

// Scratch (static device globals — no allocations allowed)
__device__ float          g_feat [ROWS*HU];
__device__ float          g_resid[ROWS*HU];
__device__ __nv_bfloat16  g_fbf  [ROWS*HU];   // bf16 shadow of g_feat (gather path)
__device__ float          g_aself[ROWS*HDIM];
__device__ float          g_aneigh[ROWS*HDIM];

// ---------------------------------------------------------------------------
// Kernel A: fp32 GEMM, C = X[8192,256] @ W[256,512]  (R1 version, 116.8us)
// blockIdx.z selects (kernel -> g_feat) or (kernel_residual -> g_resid).
// 128x128 tile, BK=16, 256 threads, 8x8 microtile per thread.
// ---------------------------------------------------------------------------
__global__ __launch_bounds__(256) void proj_gemm(const float* __restrict__ Xg,
                                                 const float* __restrict__ W0,
                                                 const float* __restrict__ W1)
{
    const float* W = (blockIdx.z == 0) ? W0 : W1;
    float*       C = (blockIdx.z == 0) ? g_feat : g_resid;

    __shared__ __align__(16) float As[16][132];  // transposed [k][m], +4 pad
    __shared__ __align__(16) float Bs[16][128];

    const int tid = threadIdx.x;
    const int bm  = blockIdx.y * 128;
    const int bn  = blockIdx.x * 128;
    const int tx  = tid & 15;
    const int ty  = tid >> 4;

    float acc[8][8];
#pragma unroll
    for (int i = 0; i < 8; i++)
#pragma unroll
        for (int j = 0; j < 8; j++) acc[i][j] = 0.f;

    for (int k0 = 0; k0 < DDIM; k0 += 16) {
#pragma unroll
        for (int i = 0; i < 2; i++) {
            int idx = tid * 2 + i;            // 0..511 float4s
            int r   = idx >> 2;               // row 0..127
            int c4  = (idx & 3) << 2;         // col group 0,4,8,12
            float4 v = *(const float4*)(Xg + (size_t)(bm + r) * DDIM + k0 + c4);
            As[c4 + 0][r] = v.x;
            As[c4 + 1][r] = v.y;
            As[c4 + 2][r] = v.z;
            As[c4 + 3][r] = v.w;
        }
#pragma unroll
        for (int i = 0; i < 2; i++) {
            int idx = tid * 2 + i;            // 0..511 float4s
            int r   = idx >> 5;               // k row 0..15
            int c4  = (idx & 31) << 2;        // col 0..124 step 4
            *(float4*)&Bs[r][c4] =
                *(const float4*)(W + (size_t)(k0 + r) * HU + bn + c4);
        }
        __syncthreads();

#pragma unroll
        for (int kk = 0; kk < 16; kk++) {
            float a[8], b[8];
            *(float4*)(a)     = *(const float4*)&As[kk][ty * 8];
            *(float4*)(a + 4) = *(const float4*)&As[kk][ty * 8 + 4];
            *(float4*)(b)     = *(const float4*)&Bs[kk][tx * 8];
            *(float4*)(b + 4) = *(const float4*)&Bs[kk][tx * 8 + 4];
#pragma unroll
            for (int i = 0; i < 8; i++)
#pragma unroll
                for (int j = 0; j < 8; j++)
                    acc[i][j] = fmaf(a[i], b[j], acc[i][j]);
        }
        __syncthreads();
    }

#pragma unroll
    for (int i = 0; i < 8; i++) {
        size_t off = (size_t)(bm + ty * 8 + i) * HU + bn + tx * 8;
        *(float4*)(C + off)     = make_float4(acc[i][0], acc[i][1], acc[i][2], acc[i][3]);
        *(float4*)(C + off + 4) = make_float4(acc[i][4], acc[i][5], acc[i][6], acc[i][7]);
    }
}

// ---------------------------------------------------------------------------
// Kernel B: per-row additive-attention logits + bf16 shadow copy of f.
// ---------------------------------------------------------------------------
__global__ __launch_bounds__(512) void attn_logits(const float* __restrict__ aks,
                                                   const float* __restrict__ akn)
{
    const int row = blockIdx.x;
    const int tid = threadIdx.x;

    float fv = g_feat[(size_t)row * HU + tid];

    // bf16 shadow write (pairwise via shfl, 4B stores from even lanes)
    float fo = __shfl_down_sync(0xffffffffu, fv, 1);
    if ((tid & 1) == 0) {
        __nv_bfloat162 p = __floats2bfloat162_rn(fv, fo);
        *(__nv_bfloat162*)(g_fbf + (size_t)row * HU + tid) = p;
    }

    float s  = fv * aks[tid];
    float nn = fv * akn[tid];
#pragma unroll
    for (int off = 16; off; off >>= 1) {
        s  += __shfl_xor_sync(0xffffffffu, s,  off);
        nn += __shfl_xor_sync(0xffffffffu, nn, off);
    }
    __shared__ float ps[16], pn[16];
    int warp = tid >> 5;
    if ((tid & 31) == 0) { ps[warp] = s; pn[warp] = nn; }
    __syncthreads();
    if (tid < HDIM) {
        g_aself [row * HDIM + tid] = ps[2 * tid] + ps[2 * tid + 1];
        g_aneigh[row * HDIM + tid] = pn[2 * tid] + pn[2 * tid + 1];
    }
}

// ---------------------------------------------------------------------------
// Kernel C: sparse masked softmax + neighborhood aggregation + epilogue.
// Aggregation: LDG.128 gathers (bf16x8/thread), 4 edge-groups of 64 threads,
// cross-group reduction in smem at the end.
// ---------------------------------------------------------------------------
__global__ __launch_bounds__(256) void gat_agg(const float* __restrict__ A,
                                               const float* __restrict__ bias,
                                               float* __restrict__ out)
{
    const int row  = blockIdx.x;      // b*1024 + n
    const int b    = row >> 10;
    const int tid  = threadIdx.x;
    const int lane = tid & 31;
    const int warp = tid >> 5;

    __shared__ int   nidx[NDIM];
    __shared__ float w[NDIM * HDIM];      // 32 KB: per-edge per-head weight
    __shared__ int   s_cnt;
    __shared__ float aself[HDIM];
    __shared__ float wred[8][HDIM];
    __shared__ float hval[HDIM];

    if (tid == 0) s_cnt = 0;
    if (tid < HDIM) aself[tid] = g_aself[row * HDIM + tid];
    __syncthreads();

    // ---- collect edges: A[b,n,:] is exactly 0.0/1.0 ----
    {
        float4 av = *(const float4*)(A + (size_t)row * NDIM + tid * 4);
        int base = tid * 4;
        if (av.x != 0.f) nidx[atomicAdd(&s_cnt, 1)] = base;
        if (av.y != 0.f) nidx[atomicAdd(&s_cnt, 1)] = base + 1;
        if (av.z != 0.f) nidx[atomicAdd(&s_cnt, 1)] = base + 2;
        if (av.w != 0.f) nidx[atomicAdd(&s_cnt, 1)] = base + 3;
    }
    __syncthreads();
    const int nnz = s_cnt;

    // ---- logits + per-head running max ----
    float lmax[HDIM];
#pragma unroll
    for (int h = 0; h < HDIM; h++) lmax[h] = -INFINITY;
    const float* an_b = g_aneigh + (size_t)b * NDIM * HDIM;
    for (int e = tid; e < nnz; e += 256) {
        int k = nidx[e];
        const float* an = an_b + k * HDIM;
#pragma unroll
        for (int h = 0; h < HDIM; h++) {
            float x = aself[h] + an[h];
            x = (x > 0.f) ? x : 0.2f * x;          // leaky_relu(0.2)
            w[e * HDIM + h] = x;
            lmax[h] = fmaxf(lmax[h], x);
        }
    }
#pragma unroll
    for (int h = 0; h < HDIM; h++)
#pragma unroll
        for (int off = 16; off; off >>= 1)
            lmax[h] = fmaxf(lmax[h], __shfl_xor_sync(0xffffffffu, lmax[h], off));
    if (lane == 0) {
#pragma unroll
        for (int h = 0; h < HDIM; h++) wred[warp][h] = lmax[h];
    }
    __syncthreads();
    if (tid < HDIM) {
        float m = wred[0][tid];
#pragma unroll
        for (int wp = 1; wp < 8; wp++) m = fmaxf(m, wred[wp][tid]);
        hval[tid] = m;
    }
    __syncthreads();
    float hm[HDIM];
#pragma unroll
    for (int h = 0; h < HDIM; h++) hm[h] = hval[h];

    // ---- exp + per-head sum ----
    float lsum[HDIM];
#pragma unroll
    for (int h = 0; h < HDIM; h++) lsum[h] = 0.f;
    for (int e = tid; e < nnz; e += 256) {
#pragma unroll
        for (int h = 0; h < HDIM; h++) {
            float v = __expf(w[e * HDIM + h] - hm[h]);
            w[e * HDIM + h] = v;
            lsum[h] += v;
        }
    }
#pragma unroll
    for (int h = 0; h < HDIM; h++)
#pragma unroll
        for (int off = 16; off; off >>= 1)
            lsum[h] += __shfl_xor_sync(0xffffffffu, lsum[h], off);
    if (lane == 0) {
#pragma unroll
        for (int h = 0; h < HDIM; h++) wred[warp][h] = lsum[h];
    }
    __syncthreads();
    if (tid < HDIM) {
        float s = 0.f;
#pragma unroll
        for (int wp = 0; wp < 8; wp++) s += wred[wp][tid];
        hval[tid] = 1.0f / s;
    }
    __syncthreads();
#pragma unroll
    for (int h = 0; h < HDIM; h++) hm[h] = hval[h];   // inverse sums now
    for (int e = tid; e < nnz; e += 256) {
#pragma unroll
        for (int h = 0; h < HDIM; h++) w[e * HDIM + h] *= hm[h];
    }
    __syncthreads();

    // ---- aggregate with wide gathers ----
    // 4 groups of 64 threads; group g handles edges g, g+4, g+8, ...
    // Each thread covers 8 units (one LDG.128 of bf16x8) in a single head.
    const int grp = tid >> 6;         // 0..3
    const int l   = tid & 63;         // 0..63
    const int hh  = l >> 3;           // head of this 8-unit slice
    const int u8  = l * 8;            // first unit (0..504)
    const __nv_bfloat16* fb = g_fbf + (size_t)b * NDIM * HU + u8;

    float acc[8];
#pragma unroll
    for (int i = 0; i < 8; i++) acc[i] = 0.f;

#pragma unroll 2
    for (int e = grp; e < nnz; e += 4) {
        int   k = nidx[e];
        float c = w[e * HDIM + hh];
        uint4 p = *(const uint4*)(fb + (size_t)k * HU);
        float2 f0 = __bfloat1622float2(*(__nv_bfloat162*)&p.x);
        float2 f1 = __bfloat1622float2(*(__nv_bfloat162*)&p.y);
        float2 f2 = __bfloat1622float2(*(__nv_bfloat162*)&p.z);
        float2 f3 = __bfloat1622float2(*(__nv_bfloat162*)&p.w);
        acc[0] = fmaf(c, f0.x, acc[0]);
        acc[1] = fmaf(c, f0.y, acc[1]);
        acc[2] = fmaf(c, f1.x, acc[2]);
        acc[3] = fmaf(c, f1.y, acc[3]);
        acc[4] = fmaf(c, f2.x, acc[4]);
        acc[5] = fmaf(c, f2.y, acc[5]);
        acc[6] = fmaf(c, f3.x, acc[6]);
        acc[7] = fmaf(c, f3.y, acc[7]);
    }
    __syncthreads();                      // done reading w; reuse as reduction buf

    float* red = w;                       // 4 * 512 floats = 8 KB
    *(float4*)&red[grp * HU + u8]     = make_float4(acc[0], acc[1], acc[2], acc[3]);
    *(float4*)&red[grp * HU + u8 + 4] = make_float4(acc[4], acc[5], acc[6], acc[7]);
    __syncthreads();

    // thread t finishes units 2t, 2t+1
    const int u = 2 * tid;
    size_t o = (size_t)row * HU + u;
    float2 rres = *(const float2*)(g_resid + o);
    float s0 = red[u]     + red[HU + u]     + red[2 * HU + u]     + red[3 * HU + u];
    float s1 = red[u + 1] + red[HU + u + 1] + red[2 * HU + u + 1] + red[3 * HU + u + 1];
    float r0 = s0 + rres.x + bias[u];
    float r1 = s1 + rres.y + bias[u + 1];
    float2 ro;
    ro.x = (r0 > 0.f) ? r0 : 0.f;
    ro.y = (r1 > 0.f) ? r1 : 0.f;
    *(float2*)(out + o) = ro;
}

// ---------------------------------------------------------------------------
extern "C" void kernel_launch(void* const* d_in, const int* in_sizes, int n_in,
                              void* d_out, int out_size)
{
    const float* X    = (const float*)d_in[0];  // [8,1024,256]
    const float* A    = (const float*)d_in[1];  // [8,1024,1024]
    const float* Wk   = (const float*)d_in[2];  // [256,512]
    const float* Wr   = (const float*)d_in[3];  // [256,512]
    const float* aks  = (const float*)d_in[4];  // [8,64,1] -> flat 512
    const float* akn  = (const float*)d_in[5];  // [8,64,1] -> flat 512
    const float* bias = (const float*)d_in[6];  // [512]
    float*       out  = (float*)d_out;          // [8,1024,512]

    (void)in_sizes; (void)n_in; (void)out_size;

    dim3 g(HU / 128, ROWS / 128, 2);
    proj_gemm<<<g, 256>>>(X, Wk, Wr);
    attn_logits<<<ROWS, 512>>>(aks, akn);
    gat_agg<<<ROWS, 256>>>(A, bias, out);
}

// round 4
// speedup vs baseline: 1.6764x; 1.2721x over previous
#include <cuda_runtime.h>
#include <cuda_bf16.h>
#include <math.h>

#define BDIM 8
#define NDIM 1024
#define DDIM 256
#define HDIM 8
#define UDIM 64
#define HU   512
#define ROWS (BDIM*NDIM)   // 8192

// Scratch (static device globals — no allocations allowed)
__device__ float          g_feat [ROWS*HU];
__device__ float          g_resid[ROWS*HU];
__device__ __nv_bfloat16  g_fbf  [ROWS*HU];   // bf16 shadow of g_feat (gather path)
__device__ float          g_aself[ROWS*HDIM];
__device__ float          g_aneigh[ROWS*HDIM];

__device__ __forceinline__ unsigned f2tf32(float x) {
    unsigned u;
    asm("cvt.rna.tf32.f32 %0, %1;" : "=r"(u) : "f"(x));
    return u;
}

// ---------------------------------------------------------------------------
// Kernel A1: TF32 tensor-core GEMM for the FEATURE projection.
// g_feat = X[8192,256] @ Wk[256,512]; also writes bf16 shadow g_fbf.
// Tile 128x64, BK=32, 256 threads (8 warps as 4x2), warp tile 32x32.
// mma.sync.m16n8k8 tf32. Downstream consumers (logits, bf16 gather) need
// far less than tf32 precision, so single-pass tf32 is safe here.
// ---------------------------------------------------------------------------
__global__ __launch_bounds__(256) void feat_gemm_tf32(const float* __restrict__ Xg,
                                                      const float* __restrict__ W)
{
    __shared__ unsigned As[128][36];   // [m][k], tf32 bits, pad->conflict-free frags
    __shared__ unsigned Bs[32][72];    // [k][n], pad 72 -> conflict-free frags

    const int tid  = threadIdx.x;
    const int lane = tid & 31;
    const int warp = tid >> 5;
    const int wm   = warp >> 1;        // 0..3
    const int wn   = warp & 1;         // 0..1
    const int bm   = blockIdx.y * 128;
    const int bn   = blockIdx.x * 64;

    float c[2][4][4];
#pragma unroll
    for (int i = 0; i < 2; i++)
#pragma unroll
        for (int j = 0; j < 4; j++)
#pragma unroll
            for (int r = 0; r < 4; r++) c[i][j][r] = 0.f;

    for (int t = 0; t < 8; t++) {
        const int k0 = t * 32;
        // A tile: 128 rows x 32 k  (1024 float4s, 4 per thread)
#pragma unroll
        for (int i = 0; i < 4; i++) {
            int idx = tid + i * 256;          // 0..1023
            int r   = idx >> 3;               // row
            int c4  = (idx & 7) << 2;         // k offset
            float4 v = *(const float4*)(Xg + (size_t)(bm + r) * DDIM + k0 + c4);
            As[r][c4 + 0] = f2tf32(v.x);
            As[r][c4 + 1] = f2tf32(v.y);
            As[r][c4 + 2] = f2tf32(v.z);
            As[r][c4 + 3] = f2tf32(v.w);
        }
        // B tile: 32 k x 64 n (512 float4s, 2 per thread)
#pragma unroll
        for (int i = 0; i < 2; i++) {
            int idx = tid + i * 256;          // 0..511
            int r   = idx >> 4;               // k row
            int c4  = (idx & 15) << 2;        // n offset
            float4 v = *(const float4*)(W + (size_t)(k0 + r) * HU + bn + c4);
            Bs[r][c4 + 0] = f2tf32(v.x);
            Bs[r][c4 + 1] = f2tf32(v.y);
            Bs[r][c4 + 2] = f2tf32(v.z);
            Bs[r][c4 + 3] = f2tf32(v.w);
        }
        __syncthreads();

#pragma unroll
        for (int kk = 0; kk < 4; kk++) {
            unsigned a[2][4], b[4][2];
            const int ar = wm * 32 + (lane >> 2);
            const int ac = kk * 8 + (lane & 3);
#pragma unroll
            for (int i = 0; i < 2; i++) {
                a[i][0] = As[ar + i * 16][ac];
                a[i][1] = As[ar + i * 16 + 8][ac];
                a[i][2] = As[ar + i * 16][ac + 4];
                a[i][3] = As[ar + i * 16 + 8][ac + 4];
            }
            const int br = kk * 8 + (lane & 3);
            const int bc = wn * 32 + (lane >> 2);
#pragma unroll
            for (int j = 0; j < 4; j++) {
                b[j][0] = Bs[br][bc + j * 8];
                b[j][1] = Bs[br + 4][bc + j * 8];
            }
#pragma unroll
            for (int i = 0; i < 2; i++)
#pragma unroll
                for (int j = 0; j < 4; j++) {
                    asm volatile(
                        "mma.sync.aligned.m16n8k8.row.col.f32.tf32.tf32.f32 "
                        "{%0,%1,%2,%3}, {%4,%5,%6,%7}, {%8,%9}, {%0,%1,%2,%3};"
                        : "+f"(c[i][j][0]), "+f"(c[i][j][1]),
                          "+f"(c[i][j][2]), "+f"(c[i][j][3])
                        : "r"(a[i][0]), "r"(a[i][1]), "r"(a[i][2]), "r"(a[i][3]),
                          "r"(b[j][0]), "r"(b[j][1]));
                }
        }
        __syncthreads();
    }

    // epilogue: fp32 to g_feat, bf16 shadow to g_fbf
#pragma unroll
    for (int i = 0; i < 2; i++) {
        int row0 = bm + wm * 32 + i * 16 + (lane >> 2);
#pragma unroll
        for (int j = 0; j < 4; j++) {
            int col = bn + wn * 32 + j * 8 + 2 * (lane & 3);
            size_t o0 = (size_t)row0 * HU + col;
            size_t o1 = (size_t)(row0 + 8) * HU + col;
            *(float2*)(g_feat + o0) = make_float2(c[i][j][0], c[i][j][1]);
            *(float2*)(g_feat + o1) = make_float2(c[i][j][2], c[i][j][3]);
            *(__nv_bfloat162*)(g_fbf + o0) = __floats2bfloat162_rn(c[i][j][0], c[i][j][1]);
            *(__nv_bfloat162*)(g_fbf + o1) = __floats2bfloat162_rn(c[i][j][2], c[i][j][3]);
        }
    }
}

// ---------------------------------------------------------------------------
// Kernel A2: fp32 GEMM for the RESIDUAL projection (exact path).
// g_resid = X @ Wr. 128x128 tile, BK=16, 256 threads, 8x8 microtile.
// ---------------------------------------------------------------------------
__global__ __launch_bounds__(256) void resid_gemm(const float* __restrict__ Xg,
                                                  const float* __restrict__ W)
{
    float* C = g_resid;

    __shared__ __align__(16) float As[16][132];
    __shared__ __align__(16) float Bs[16][128];

    const int tid = threadIdx.x;
    const int bm  = blockIdx.y * 128;
    const int bn  = blockIdx.x * 128;
    const int tx  = tid & 15;
    const int ty  = tid >> 4;

    float acc[8][8];
#pragma unroll
    for (int i = 0; i < 8; i++)
#pragma unroll
        for (int j = 0; j < 8; j++) acc[i][j] = 0.f;

    for (int k0 = 0; k0 < DDIM; k0 += 16) {
#pragma unroll
        for (int i = 0; i < 2; i++) {
            int idx = tid * 2 + i;
            int r   = idx >> 2;
            int c4  = (idx & 3) << 2;
            float4 v = *(const float4*)(Xg + (size_t)(bm + r) * DDIM + k0 + c4);
            As[c4 + 0][r] = v.x;
            As[c4 + 1][r] = v.y;
            As[c4 + 2][r] = v.z;
            As[c4 + 3][r] = v.w;
        }
#pragma unroll
        for (int i = 0; i < 2; i++) {
            int idx = tid * 2 + i;
            int r   = idx >> 5;
            int c4  = (idx & 31) << 2;
            *(float4*)&Bs[r][c4] =
                *(const float4*)(W + (size_t)(k0 + r) * HU + bn + c4);
        }
        __syncthreads();

#pragma unroll
        for (int kk = 0; kk < 16; kk++) {
            float a[8], b[8];
            *(float4*)(a)     = *(const float4*)&As[kk][ty * 8];
            *(float4*)(a + 4) = *(const float4*)&As[kk][ty * 8 + 4];
            *(float4*)(b)     = *(const float4*)&Bs[kk][tx * 8];
            *(float4*)(b + 4) = *(const float4*)&Bs[kk][tx * 8 + 4];
#pragma unroll
            for (int i = 0; i < 8; i++)
#pragma unroll
                for (int j = 0; j < 8; j++)
                    acc[i][j] = fmaf(a[i], b[j], acc[i][j]);
        }
        __syncthreads();
    }

#pragma unroll
    for (int i = 0; i < 8; i++) {
        size_t off = (size_t)(bm + ty * 8 + i) * HU + bn + tx * 8;
        *(float4*)(C + off)     = make_float4(acc[i][0], acc[i][1], acc[i][2], acc[i][3]);
        *(float4*)(C + off + 4) = make_float4(acc[i][4], acc[i][5], acc[i][6], acc[i][7]);
    }
}

// ---------------------------------------------------------------------------
// Kernel B: per-row additive-attention logits.
// ---------------------------------------------------------------------------
__global__ __launch_bounds__(512) void attn_logits(const float* __restrict__ aks,
                                                   const float* __restrict__ akn)
{
    const int row = blockIdx.x;
    const int tid = threadIdx.x;

    float fv = g_feat[(size_t)row * HU + tid];
    float s  = fv * aks[tid];
    float nn = fv * akn[tid];
#pragma unroll
    for (int off = 16; off; off >>= 1) {
        s  += __shfl_xor_sync(0xffffffffu, s,  off);
        nn += __shfl_xor_sync(0xffffffffu, nn, off);
    }
    __shared__ float ps[16], pn[16];
    int warp = tid >> 5;
    if ((tid & 31) == 0) { ps[warp] = s; pn[warp] = nn; }
    __syncthreads();
    if (tid < HDIM) {
        g_aself [row * HDIM + tid] = ps[2 * tid] + ps[2 * tid + 1];
        g_aneigh[row * HDIM + tid] = pn[2 * tid] + pn[2 * tid + 1];
    }
}

// ---------------------------------------------------------------------------
// Kernel C: sparse masked softmax + neighborhood aggregation + epilogue.
// Ballot-compacted edge list (no serialized atomics), softmax normalization
// folded into gather epilogue, LDG.128 bf16 gathers.
// ---------------------------------------------------------------------------
__global__ __launch_bounds__(256) void gat_agg(const float* __restrict__ A,
                                               const float* __restrict__ bias,
                                               float* __restrict__ out)
{
    const int row  = blockIdx.x;      // b*1024 + n
    const int b    = row >> 10;
    const int tid  = threadIdx.x;
    const int lane = tid & 31;
    const int warp = tid >> 5;

    __shared__ int   nidx[NDIM];
    __shared__ float w[NDIM * HDIM];      // 32 KB: per-edge per-head exp weight
    __shared__ int   wcnt[8];
    __shared__ float aself[HDIM];
    __shared__ float wred[8][HDIM];
    __shared__ float hval[HDIM];

    if (tid < HDIM) aself[tid] = g_aself[row * HDIM + tid];

    // ---- collect edges via warp ballots (A entries are exactly 0.0/1.0) ----
    const int base_col = warp * 128 + lane * 4;
    float4 av = *(const float4*)(A + (size_t)row * NDIM + base_col);
    unsigned m0 = __ballot_sync(0xffffffffu, av.x != 0.f);
    unsigned m1 = __ballot_sync(0xffffffffu, av.y != 0.f);
    unsigned m2 = __ballot_sync(0xffffffffu, av.z != 0.f);
    unsigned m3 = __ballot_sync(0xffffffffu, av.w != 0.f);
    int cnt = __popc(m0) + __popc(m1) + __popc(m2) + __popc(m3);
    if (lane == 0) wcnt[warp] = cnt;
    __syncthreads();
    int wbase = 0, nnz = 0;
#pragma unroll
    for (int ww = 0; ww < 8; ww++) {
        int c = wcnt[ww];
        wbase += (ww < warp) ? c : 0;
        nnz += c;
    }
    const unsigned lt = (1u << lane) - 1u;
    int off = wbase;
    if (av.x != 0.f) nidx[off + __popc(m0 & lt)] = base_col;
    off += __popc(m0);
    if (av.y != 0.f) nidx[off + __popc(m1 & lt)] = base_col + 1;
    off += __popc(m1);
    if (av.z != 0.f) nidx[off + __popc(m2 & lt)] = base_col + 2;
    off += __popc(m2);
    if (av.w != 0.f) nidx[off + __popc(m3 & lt)] = base_col + 3;
    __syncthreads();

    // ---- logits + per-head running max ----
    float lmax[HDIM];
#pragma unroll
    for (int h = 0; h < HDIM; h++) lmax[h] = -INFINITY;
    const float* an_b = g_aneigh + (size_t)b * NDIM * HDIM;
    for (int e = tid; e < nnz; e += 256) {
        int k = nidx[e];
        const float4* an4 = (const float4*)(an_b + (size_t)k * HDIM);
        float4 p0 = an4[0], p1 = an4[1];
        float xv[HDIM] = {p0.x, p0.y, p0.z, p0.w, p1.x, p1.y, p1.z, p1.w};
#pragma unroll
        for (int h = 0; h < HDIM; h++) {
            float x = aself[h] + xv[h];
            x = (x > 0.f) ? x : 0.2f * x;          // leaky_relu(0.2)
            w[e * HDIM + h] = x;
            lmax[h] = fmaxf(lmax[h], x);
        }
    }
#pragma unroll
    for (int h = 0; h < HDIM; h++)
#pragma unroll
        for (int o2 = 16; o2; o2 >>= 1)
            lmax[h] = fmaxf(lmax[h], __shfl_xor_sync(0xffffffffu, lmax[h], o2));
    if (lane == 0) {
#pragma unroll
        for (int h = 0; h < HDIM; h++) wred[warp][h] = lmax[h];
    }
    __syncthreads();
    if (tid < HDIM) {
        float m = wred[0][tid];
#pragma unroll
        for (int wp = 1; wp < 8; wp++) m = fmaxf(m, wred[wp][tid]);
        hval[tid] = m;
    }
    __syncthreads();
    float hm[HDIM];
#pragma unroll
    for (int h = 0; h < HDIM; h++) hm[h] = hval[h];

    // ---- exp + per-head sum (store unnormalized exp in w) ----
    float lsum[HDIM];
#pragma unroll
    for (int h = 0; h < HDIM; h++) lsum[h] = 0.f;
    for (int e = tid; e < nnz; e += 256) {
#pragma unroll
        for (int h = 0; h < HDIM; h++) {
            float v = __expf(w[e * HDIM + h] - hm[h]);
            w[e * HDIM + h] = v;
            lsum[h] += v;
        }
    }
#pragma unroll
    for (int h = 0; h < HDIM; h++)
#pragma unroll
        for (int o2 = 16; o2; o2 >>= 1)
            lsum[h] += __shfl_xor_sync(0xffffffffu, lsum[h], o2);
    if (lane == 0) {
#pragma unroll
        for (int h = 0; h < HDIM; h++) wred[warp][h] = lsum[h];
    }
    __syncthreads();
    if (tid < HDIM) {
        float s = 0.f;
#pragma unroll
        for (int wp = 0; wp < 8; wp++) s += wred[wp][tid];
        hval[tid] = 1.0f / s;                 // inverse softmax denominator
    }
    __syncthreads();

    // ---- aggregate with wide gathers (normalization folded in) ----
    // 4 groups of 64 threads; group g handles edges g, g+4, g+8, ...
    // Each thread covers 8 units (one LDG.128 of bf16x8) in a single head.
    const int grp = tid >> 6;         // 0..3
    const int l   = tid & 63;         // 0..63
    const int hh  = l >> 3;           // head of this 8-unit slice
    const int u8  = l * 8;            // first unit (0..504)
    const float inv = hval[hh];
    const __nv_bfloat16* fb = g_fbf + (size_t)b * NDIM * HU + u8;

    float acc[8];
#pragma unroll
    for (int i = 0; i < 8; i++) acc[i] = 0.f;

#pragma unroll 4
    for (int e = grp; e < nnz; e += 4) {
        int   k = nidx[e];
        float c = w[e * HDIM + hh];
        uint4 p = *(const uint4*)(fb + (size_t)k * HU);
        float2 f0 = __bfloat1622float2(*(__nv_bfloat162*)&p.x);
        float2 f1 = __bfloat1622float2(*(__nv_bfloat162*)&p.y);
        float2 f2 = __bfloat1622float2(*(__nv_bfloat162*)&p.z);
        float2 f3 = __bfloat1622float2(*(__nv_bfloat162*)&p.w);
        acc[0] = fmaf(c, f0.x, acc[0]);
        acc[1] = fmaf(c, f0.y, acc[1]);
        acc[2] = fmaf(c, f1.x, acc[2]);
        acc[3] = fmaf(c, f1.y, acc[3]);
        acc[4] = fmaf(c, f2.x, acc[4]);
        acc[5] = fmaf(c, f2.y, acc[5]);
        acc[6] = fmaf(c, f3.x, acc[6]);
        acc[7] = fmaf(c, f3.y, acc[7]);
    }
#pragma unroll
    for (int i = 0; i < 8; i++) acc[i] *= inv;
    __syncthreads();                      // done reading w; reuse as reduction buf

    float* red = w;                       // 4 * 512 floats = 8 KB
    *(float4*)&red[grp * HU + u8]     = make_float4(acc[0], acc[1], acc[2], acc[3]);
    *(float4*)&red[grp * HU + u8 + 4] = make_float4(acc[4], acc[5], acc[6], acc[7]);
    __syncthreads();

    // thread t finishes units 2t, 2t+1
    const int u = 2 * tid;
    size_t o = (size_t)row * HU + u;
    float2 rres = *(const float2*)(g_resid + o);
    float s0 = red[u]     + red[HU + u]     + red[2 * HU + u]     + red[3 * HU + u];
    float s1 = red[u + 1] + red[HU + u + 1] + red[2 * HU + u + 1] + red[3 * HU + u + 1];
    float r0 = s0 + rres.x + bias[u];
    float r1 = s1 + rres.y + bias[u + 1];
    float2 ro;
    ro.x = (r0 > 0.f) ? r0 : 0.f;
    ro.y = (r1 > 0.f) ? r1 : 0.f;
    *(float2*)(out + o) = ro;
}

// ---------------------------------------------------------------------------
extern "C" void kernel_launch(void* const* d_in, const int* in_sizes, int n_in,
                              void* d_out, int out_size)
{
    const float* X    = (const float*)d_in[0];  // [8,1024,256]
    const float* A    = (const float*)d_in[1];  // [8,1024,1024]
    const float* Wk   = (const float*)d_in[2];  // [256,512]
    const float* Wr   = (const float*)d_in[3];  // [256,512]
    const float* aks  = (const float*)d_in[4];  // [8,64,1] -> flat 512
    const float* akn  = (const float*)d_in[5];  // [8,64,1] -> flat 512
    const float* bias = (const float*)d_in[6];  // [512]
    float*       out  = (float*)d_out;          // [8,1024,512]

    (void)in_sizes; (void)n_in; (void)out_size;

    feat_gemm_tf32<<<dim3(HU / 64, ROWS / 128), 256>>>(X, Wk);
    resid_gemm<<<dim3(HU / 128, ROWS / 128), 256>>>(X, Wr);
    attn_logits<<<ROWS, 512>>>(aks, akn);
    gat_agg<<<ROWS, 256>>>(A, bias, out);
}